// round 1
// baseline (speedup 1.0000x reference)
#include <cuda_runtime.h>
#include <cuda_bf16.h>

// Problem constants
#define BB 8
#define NN 2048
#define DD 128
#define N_LAYER 4
#define N_HEAD 8
#define MAT (DD*DD)            // 16384 floats per 128x128 matrix
#define G0_CHUNKS 16           // split N=2048 into 16 chunks of 128 rows

// ----------------------------- scratch (device globals; no allocation) ----
__device__ __align__(16) float g_part[G0_CHUNKS * BB * MAT]; // 8 MB partial G
__device__ __align__(16) float g_G[2][BB * MAT];
__device__ __align__(16) float g_A[2][BB * MAT];
__device__ __align__(16) float g_T[BB * N_HEAD * MAT];       // 4 MB
__device__ __align__(16) float g_Wp[BB * N_HEAD * MAT];      // 4 MB
__device__ __align__(16) float g_M[BB * MAT];
__device__ __align__(16) float g_P[BB * MAT];

// ----------------------------- core 32x128 GEMM tile (K = 128) ------------
// C[32x128] = op(A)[32x128] @ op(B)[128x128]
// TA: op(A)[m,k] = A[k*lda + m]   else A[m*lda + k]
// TB: op(B)[k,n] = B[n*ldb + k]   else B[k*ldb + n]
template<bool TA, bool TB>
__device__ __forceinline__ void gemm_32x128(const float* __restrict__ A, int lda,
                                            const float* __restrict__ B, int ldb,
                                            float* __restrict__ C)
{
    __shared__ __align__(16) float As[32][33];
    __shared__ __align__(16) float Bs[32][132];

    const int tid = threadIdx.x;       // 256 threads
    const int g   = tid >> 5;          // 0..7  -> rows g*4 .. g*4+3
    const int col = (tid & 31) * 4;    // 0..124

    float acc[4][4];
#pragma unroll
    for (int r = 0; r < 4; r++)
#pragma unroll
        for (int c = 0; c < 4; c++) acc[r][c] = 0.0f;

    for (int k0 = 0; k0 < 128; k0 += 32) {
        // --- load A tile (32x32) ---
#pragma unroll
        for (int t = 0; t < 4; t++) {
            int i = tid + t * 256;
            if (!TA) { int m = i >> 5, k = i & 31; As[m][k] = A[m * lda + k0 + k]; }
            else     { int k = i >> 5, m = i & 31; As[m][k] = A[(k0 + k) * lda + m]; }
        }
        // --- load B tile (32x128) ---
        if (!TB) {
#pragma unroll
            for (int t = 0; t < 4; t++) {
                int v = tid + t * 256;
                int k = v >> 5, n4 = (v & 31) * 4;
                float4 x = *(const float4*)&B[(k0 + k) * ldb + n4];
                Bs[k][n4 + 0] = x.x; Bs[k][n4 + 1] = x.y;
                Bs[k][n4 + 2] = x.z; Bs[k][n4 + 3] = x.w;
            }
        } else {
#pragma unroll
            for (int t = 0; t < 16; t++) {
                int j = tid + t * 256;
                int n = j >> 5, k = j & 31;
                Bs[k][n] = B[n * ldb + k0 + k];
            }
        }
        __syncthreads();

#pragma unroll
        for (int kk = 0; kk < 32; kk++) {
            float4 bv = *(const float4*)&Bs[kk][col];
#pragma unroll
            for (int r = 0; r < 4; r++) {
                float a = As[g * 4 + r][kk];
                acc[r][0] += a * bv.x;
                acc[r][1] += a * bv.y;
                acc[r][2] += a * bv.z;
                acc[r][3] += a * bv.w;
            }
        }
        __syncthreads();
    }

#pragma unroll
    for (int r = 0; r < 4; r++) {
        float4 o = make_float4(acc[r][0], acc[r][1], acc[r][2], acc[r][3]);
        *(float4*)&C[(g * 4 + r) * 128 + col] = o;
    }
}

// ----------------------------- kernels ------------------------------------

// partial G0: for each (chunk, b): part = Zc^T @ Zc, Zc = 128 rows of Z
__global__ __launch_bounds__(256) void k_g0(const float* __restrict__ Z,
                                            float* __restrict__ part)
{
    int chunk = blockIdx.x, b = blockIdx.y, rt = blockIdx.z;
    const float* Zc = Z + (b * NN + chunk * 128) * DD;
    gemm_32x128<true, false>(Zc + rt * 32, DD, Zc, DD,
                             part + (chunk * BB + b) * MAT + rt * 32 * 128);
}

__global__ __launch_bounds__(256) void k_greduce(const float* __restrict__ part,
                                                 float* __restrict__ G)
{
    int e = blockIdx.x * 256 + threadIdx.x;      // 131072 total
    int b = e >> 14, i = e & 16383;
    float s = 0.0f;
#pragma unroll
    for (int c = 0; c < G0_CHUNKS; c++) s += part[(c * BB + b) * MAT + i];
    G[e] = s;
}

__global__ __launch_bounds__(256) void k_initA(float* __restrict__ A)
{
    int e = blockIdx.x * 256 + threadIdx.x;
    int i = e & 16383;
    A[e] = ((i >> 7) == (i & 127)) ? 1.0f : 0.0f;
}

// T[b,j] = Q[l,j] @ G[b]
__global__ __launch_bounds__(256) void k_T(const float* __restrict__ q,
                                           const float* __restrict__ G,
                                           float* __restrict__ T, int l)
{
    int j = blockIdx.x, b = blockIdx.y, rt = blockIdx.z;
    gemm_32x128<false, false>(q + (l * N_HEAD + j) * MAT + rt * 32 * 128, 128,
                              G + b * MAT, 128,
                              T + (b * N_HEAD + j) * MAT + rt * 32 * 128);
}

// Wp[b,j] = T[b,j] @ V[l,j]^T
__global__ __launch_bounds__(256) void k_Wp(const float* __restrict__ T,
                                            const float* __restrict__ v,
                                            float* __restrict__ Wp, int l)
{
    int j = blockIdx.x, b = blockIdx.y, rt = blockIdx.z;
    gemm_32x128<false, true>(T + (b * N_HEAD + j) * MAT + rt * 32 * 128, 128,
                             v + (l * N_HEAD + j) * MAT, 128,
                             Wp + (b * N_HEAD + j) * MAT + rt * 32 * 128);
}

// M[b] = I + (sum_j Wp[b,j]) / (N*N_HEAD)
__global__ __launch_bounds__(256) void k_M(const float* __restrict__ Wp,
                                           float* __restrict__ M)
{
    int e = blockIdx.x * 256 + threadIdx.x;      // 131072 total
    int b = e >> 14, i = e & 16383;
    float s = 0.0f;
#pragma unroll
    for (int j = 0; j < N_HEAD; j++) s += Wp[(b * N_HEAD + j) * MAT + i];
    float id = ((i >> 7) == (i & 127)) ? 1.0f : 0.0f;
    M[e] = id + s * (1.0f / (float(NN) * float(N_HEAD)));
}

// which=0: Anew = A @ M ; which=1: P = G @ M
__global__ __launch_bounds__(256) void k_PA(const float* __restrict__ G,
                                            const float* __restrict__ A,
                                            const float* __restrict__ M,
                                            float* __restrict__ P,
                                            float* __restrict__ Anew)
{
    int which = blockIdx.x, b = blockIdx.y, rt = blockIdx.z;
    const float* src = which ? G : A;
    float*       dst = which ? P : Anew;
    gemm_32x128<false, false>(src + b * MAT + rt * 32 * 128, 128,
                              M + b * MAT, 128,
                              dst + b * MAT + rt * 32 * 128);
}

// Gnext[b] = M[b]^T @ P[b]
__global__ __launch_bounds__(256) void k_Gn(const float* __restrict__ M,
                                            const float* __restrict__ P,
                                            float* __restrict__ Gn)
{
    int b = blockIdx.x, rt = blockIdx.y;
    gemm_32x128<true, false>(M + b * MAT + rt * 32, 128,
                             P + b * MAT, 128,
                             Gn + b * MAT + rt * 32 * 128);
}

// out[b] = Z[b] @ A[b]
__global__ __launch_bounds__(256) void k_out(const float* __restrict__ Z,
                                             const float* __restrict__ A,
                                             float* __restrict__ out)
{
    int tile = blockIdx.x, b = blockIdx.y;   // tile 0..63 (32 rows each)
    const float* Zt = Z + (b * NN + tile * 32) * DD;
    gemm_32x128<false, false>(Zt, DD, A + b * MAT, 128,
                              out + (b * NN + tile * 32) * DD);
}

// ----------------------------- host ---------------------------------------
extern "C" void kernel_launch(void* const* d_in, const int* in_sizes, int n_in,
                              void* d_out, int out_size)
{
    const float* Z = (const float*)d_in[0];        // [8,2048,128]
    const float* v = (const float*)d_in[1];        // [4,8,1,128,128]
    const float* q = (const float*)d_in[2];        // [4,8,1,128,128]
    float* out = (float*)d_out;

    float *pPart, *pG0, *pG1, *pA0, *pA1, *pT, *pWp, *pM, *pP;
    cudaGetSymbolAddress((void**)&pPart, g_part);
    cudaGetSymbolAddress((void**)&pG0, g_G);  pG1 = pG0 + BB * MAT;
    cudaGetSymbolAddress((void**)&pA0, g_A);  pA1 = pA0 + BB * MAT;
    cudaGetSymbolAddress((void**)&pT,  g_T);
    cudaGetSymbolAddress((void**)&pWp, g_Wp);
    cudaGetSymbolAddress((void**)&pM,  g_M);
    cudaGetSymbolAddress((void**)&pP,  g_P);

    // G0 = Z^T Z per batch (chunked + reduce), A = I
    k_g0<<<dim3(G0_CHUNKS, BB, 4), 256>>>(Z, pPart);
    k_greduce<<<512, 256>>>(pPart, pG0);
    k_initA<<<512, 256>>>(pA0);

    float* Gcur = pG0; float* Gnxt = pG1;
    float* Acur = pA0; float* Anxt = pA1;

    for (int l = 0; l < N_LAYER; l++) {
        k_T <<<dim3(N_HEAD, BB, 4), 256>>>(q, Gcur, pT, l);
        k_Wp<<<dim3(N_HEAD, BB, 4), 256>>>(pT, v, pWp, l);
        k_M <<<512, 256>>>(pWp, pM);
        if (l < N_LAYER - 1) {
            k_PA<<<dim3(2, BB, 4), 256>>>(Gcur, Acur, pM, pP, Anxt);
            k_Gn<<<dim3(BB, 4), 256>>>(pM, pP, Gnxt);
        } else {
            k_PA<<<dim3(1, BB, 4), 256>>>(Gcur, Acur, pM, pP, Anxt); // A only
        }
        float* t;
        t = Gcur; Gcur = Gnxt; Gnxt = t;
        t = Acur; Acur = Anxt; Anxt = t;
    }

    k_out<<<dim3(64, BB), 256>>>(Z, Acur, out);
}